// round 14
// baseline (speedup 1.0000x reference)
#include <cuda_runtime.h>
#include <cstdint>

// ---- compile-time physical constants (match reference float32 pipeline) ----
#define T_STALL_F   (5.4f * (1.0f/100.0f))                 // 0.054
#define W_FREE_F    (1620.0f * (1.0f/60.0f) * 2.0f * 3.14159265358979323846f)
#define A_CONST     (0.129907f + 0.095724f)                // L_X + L_Y
#define R_CONST     (4.0f * 0.0254f)                       // 0.1016
#define INV_R       (1.0f / R_CONST)
#define MOI_CONST   (6.0f * (12.0f*0.0254f)*(12.0f*0.0254f) / 6.0f)  // 0.09290304
#define C_XY        (INV_R / 6.0f)                         // wheel torque -> linear accel
#define C_W         ((A_CONST * INV_R) / MOI_CONST)        // wheel torque -> angular accel

#define BLOCK 256
#define ROWS_PER_TILE (2 * BLOCK)                 // 512 rows
#define F4_PER_TILE   (ROWS_PER_TILE * 6 / 4)     // 768 float4
#define TILE_BYTES    (F4_PER_TILE * 16)          // 12288 bytes

__device__ __forceinline__ uint32_t smem_u32(const void* p) {
    return (uint32_t)__cvta_generic_to_shared(p);
}

__device__ __forceinline__ void mbar_init(uint32_t mbar, uint32_t count) {
    asm volatile("mbarrier.init.shared.b64 [%0], %1;" :: "r"(mbar), "r"(count) : "memory");
}

__device__ __forceinline__ void mbar_expect_tx(uint32_t mbar, uint32_t bytes) {
    asm volatile("mbarrier.arrive.expect_tx.shared.b64 _, [%0], %1;"
                 :: "r"(mbar), "r"(bytes) : "memory");
}

__device__ __forceinline__ void bulk_load(uint32_t dst_smem, const void* src_gmem,
                                          uint32_t bytes, uint32_t mbar) {
    asm volatile(
        "cp.async.bulk.shared::cta.global.mbarrier::complete_tx::bytes [%0], [%1], %2, [%3];"
        :: "r"(dst_smem), "l"(src_gmem), "r"(bytes), "r"(mbar) : "memory");
}

__device__ __forceinline__ void bulk_store(void* dst_gmem, uint32_t src_smem,
                                           uint32_t bytes) {
    asm volatile(
        "cp.async.bulk.global.shared::cta.bulk_group [%0], [%1], %2;"
        :: "l"(dst_gmem), "r"(src_smem), "r"(bytes) : "memory");
}

__device__ __forceinline__ void bulk_commit() {
    asm volatile("cp.async.bulk.commit_group;" ::: "memory");
}

__device__ __forceinline__ void bulk_wait_all() {
    asm volatile("cp.async.bulk.wait_group 0;" ::: "memory");
}

// mbarrier wait with HW-suspend hint
__device__ __forceinline__ void mbar_wait(uint32_t mbar, uint32_t phase) {
    uint32_t done;
    asm volatile(
        "{\n\t"
        ".reg .pred p;\n\t"
        "mbarrier.try_wait.parity.acquire.cta.shared::cta.b64 p, [%1], %2, 0x989680;\n\t"
        "selp.b32 %0, 1, 0, p;\n\t"
        "}"
        : "=r"(done) : "r"(mbar), "r"(phase) : "memory");
    if (!done) {
        asm volatile(
            "{\n\t"
            ".reg .pred P1;\n\t"
            "WAIT_LOOP_%=:\n\t"
            "mbarrier.try_wait.parity.acquire.cta.shared::cta.b64 P1, [%0], %1, 0x989680;\n\t"
            "@P1 bra.uni WAIT_DONE_%=;\n\t"
            "bra.uni WAIT_LOOP_%=;\n\t"
            "WAIT_DONE_%=:\n\t"
            "}"
            :: "r"(mbar), "r"(phase) : "memory");
    }
}

__device__ __forceinline__ void fence_async_shared() {
    asm volatile("fence.proxy.async.shared::cta;" ::: "memory");
}

__device__ __forceinline__ float sgnf(float x) {
    return (float)((x > 0.0f) - (x < 0.0f));
}

// Process one row: in r[6] = {x, y, theta, vx, vy, w}; out o[6].
__device__ __forceinline__ void process_row(const float r[6],
                                            float md0, float md1, float md2, float md3,
                                            float o[6]) {
    const float theta = r[2];
    const float vx = r[3], vy = r[4], w = r[5];

    // MUFU hardware sin/cos: |theta| ~ N(0,1), abs err ~1e-6 << 1e-3 gate
    float s, c;
    __sincosf(theta, &s, &c);

    const float lvx = fmaf(c, vx,  s * vy);
    const float lvy = fmaf(c, vy, -s * vx);

    const float wA = w * A_CONST;
    const float wv0 = (lvx - lvy - wA) * INV_R;
    const float wv1 = (lvx + lvy + wA) * INV_R;
    const float wv2 = (lvx + lvy - wA) * INV_R;
    const float wv3 = (lvx - lvy + wA) * INV_R;

    const float isd0 = (sgnf(md0 * wv0) + 1.0f) * 0.5f;
    const float isd1 = (sgnf(md1 * wv1) + 1.0f) * 0.5f;
    const float isd2 = (sgnf(md2 * wv2) + 1.0f) * 0.5f;
    const float isd3 = (sgnf(md3 * wv3) + 1.0f) * 0.5f;

    const float invWF = 1.0f / W_FREE_F;
    const float wt0 = T_STALL_F * (1.0f - fabsf(wv0) * isd0 * invWF) * md0;
    const float wt1 = T_STALL_F * (1.0f - fabsf(wv1) * isd1 * invWF) * md1;
    const float wt2 = T_STALL_F * (1.0f - fabsf(wv2) * isd2 * invWF) * md2;
    const float wt3 = T_STALL_F * (1.0f - fabsf(wv3) * isd3 * invWF) * md3;

    const float lax = (wt0 + wt1 + wt2 + wt3) * C_XY;
    const float lay = (-wt0 + wt1 + wt2 - wt3) * C_XY;
    const float laz = (-wt0 + wt1 - wt2 + wt3) * C_W;

    const float aax = fmaf(c, lax, -s * lay);
    const float aay = fmaf(s, lax,  c * lay);

    o[0] = vx; o[1] = vy; o[2] = w;
    o[3] = aax; o[4] = aay; o[5] = laz;
}

// Compute + smem-writeback for one resident tile buffer.
__device__ __forceinline__ void process_tile(float4* s4, int t,
                                             float md0, float md1, float md2, float md3) {
    float4 a = s4[3 * t + 0];
    float4 b = s4[3 * t + 1];
    float4 d = s4[3 * t + 2];

    const float r0[6] = {a.x, a.y, a.z, a.w, b.x, b.y};
    const float r1[6] = {b.z, b.w, d.x, d.y, d.z, d.w};

    float o0[6], o1[6];
    process_row(r0, md0, md1, md2, md3, o0);
    process_row(r1, md0, md1, md2, md3, o1);

    s4[3 * t + 0] = make_float4(o0[0], o0[1], o0[2], o0[3]);
    s4[3 * t + 1] = make_float4(o0[4], o0[5], o1[0], o1[1]);
    s4[3 * t + 2] = make_float4(o1[2], o1[3], o1[4], o1[5]);
}

__global__ void __launch_bounds__(BLOCK)
mecanum_kernel(const float4* __restrict__ in4,
               const float*  __restrict__ cd,
               float4* __restrict__ out4,
               int nfull, int npairs, int batch) {
    __shared__ __align__(128) float4 sbuf[2][F4_PER_TILE];     // 2 x 12 KB
    __shared__ __align__(8)  unsigned long long mbar_storage[2];

    const int bid = blockIdx.x;
    const int t = threadIdx.x;

    // motor_duty = CD2MD @ control_duty  (uniform; L2-broadcast loads)
    const float c0 = __ldg(cd + 0), c1 = __ldg(cd + 1), c2 = __ldg(cd + 2);
    const float md0 = c0 - c1 - c2;
    const float md1 = c0 + c1 + c2;
    const float md2 = c0 + c1 - c2;
    const float md3 = c0 - c1 + c2;

    if (bid < npairs) {
        const int tile0 = 2 * bid;
        const int tile1 = 2 * bid + 1;
        const bool has1 = (tile1 < nfull);

        const uint32_t mb0 = smem_u32(&mbar_storage[0]);
        const uint32_t mb1 = smem_u32(&mbar_storage[1]);

        // issue BOTH tile loads up front: 24 KB in flight per block
        if (t == 0) {
            mbar_init(mb0, 1);
            mbar_init(mb1, 1);
            fence_async_shared();
            mbar_expect_tx(mb0, TILE_BYTES);
            bulk_load(smem_u32(&sbuf[0][0]),
                      (const void*)(in4 + (size_t)tile0 * F4_PER_TILE), TILE_BYTES, mb0);
            if (has1) {
                mbar_expect_tx(mb1, TILE_BYTES);
                bulk_load(smem_u32(&sbuf[1][0]),
                          (const void*)(in4 + (size_t)tile1 * F4_PER_TILE), TILE_BYTES, mb1);
            }
        }
        __syncthreads();            // mbar init + issues visible to all threads

        // ---- tile 0 ----
        mbar_wait(mb0, 0);
        process_tile(&sbuf[0][0], t, md0, md1, md2, md3);
        __syncthreads();
        if (t == 0) {
            fence_async_shared();
            bulk_store((void*)(out4 + (size_t)tile0 * F4_PER_TILE),
                       smem_u32(&sbuf[0][0]), TILE_BYTES);
            bulk_commit();
        }

        // ---- tile 1 (its load overlapped tile 0's compute) ----
        if (has1) {
            mbar_wait(mb1, 0);
            process_tile(&sbuf[1][0], t, md0, md1, md2, md3);
            __syncthreads();
            if (t == 0) {
                fence_async_shared();
                bulk_store((void*)(out4 + (size_t)tile1 * F4_PER_TILE),
                           smem_u32(&sbuf[1][0]), TILE_BYTES);
                bulk_commit();
            }
        }

        if (t == 0) bulk_wait_all();  // stores must complete before block retires
    } else {
        // tail block: scalar per-row path for rows [nfull*512, batch)
        const float* inf = (const float*)in4;
        float* outf = (float*)out4;
        for (long long row = (long long)nfull * ROWS_PER_TILE + t;
             row < batch; row += BLOCK) {
            const long long base = row * 6;
            float r[6], o[6];
            #pragma unroll
            for (int k = 0; k < 6; ++k) r[k] = inf[base + k];
            process_row(r, md0, md1, md2, md3, o);
            #pragma unroll
            for (int k = 0; k < 6; ++k) outf[base + k] = o[k];
        }
    }
}

extern "C" void kernel_launch(void* const* d_in, const int* in_sizes, int n_in,
                              void* d_out, int out_size) {
    // inputs: [0] t (1), [1] state (B*6), [2] control_duty (3)
    const float* state = (const float*)d_in[1];
    const float* cd    = (const float*)d_in[2];
    float* out = (float*)d_out;

    const int batch  = in_sizes[1] / 6;
    const int nfull  = batch / ROWS_PER_TILE;                 // full 512-row tiles
    const int tail   = batch - nfull * ROWS_PER_TILE;
    const int npairs = (nfull + 1) / 2;                       // 2 tiles per block
    const int grid   = npairs + (tail ? 1 : 0);

    mecanum_kernel<<<grid, BLOCK>>>((const float4*)state, cd, (float4*)out,
                                    nfull, npairs, batch);
}

// round 15
// speedup vs baseline: 1.0337x; 1.0337x over previous
#include <cuda_runtime.h>
#include <cstdint>

// ---- compile-time physical constants (match reference float32 pipeline) ----
#define T_STALL_F   (5.4f * (1.0f/100.0f))                 // 0.054
#define W_FREE_F    (1620.0f * (1.0f/60.0f) * 2.0f * 3.14159265358979323846f)
#define A_CONST     (0.129907f + 0.095724f)                // L_X + L_Y
#define R_CONST     (4.0f * 0.0254f)                       // 0.1016
#define INV_R       (1.0f / R_CONST)
#define MOI_CONST   (6.0f * (12.0f*0.0254f)*(12.0f*0.0254f) / 6.0f)  // 0.09290304
#define C_XY        (INV_R / 6.0f)                         // wheel torque -> linear accel
#define C_W         ((A_CONST * INV_R) / MOI_CONST)        // wheel torque -> angular accel

#define BLOCK 256
#define SUB_ROWS   BLOCK                      // 256 rows per subtile
#define SUB_F4     (SUB_ROWS * 6 / 4)         // 384 float4
#define SUB_BYTES  (SUB_F4 * 16)              // 6144 bytes
#define ROWS_PER_BLOCK (2 * SUB_ROWS)         // 512 rows
#define F4_PER_BLOCK   (2 * SUB_F4)           // 768 float4

__device__ __forceinline__ uint32_t smem_u32(const void* p) {
    return (uint32_t)__cvta_generic_to_shared(p);
}

__device__ __forceinline__ void mbar_init(uint32_t mbar, uint32_t count) {
    asm volatile("mbarrier.init.shared.b64 [%0], %1;" :: "r"(mbar), "r"(count) : "memory");
}

__device__ __forceinline__ void mbar_expect_tx(uint32_t mbar, uint32_t bytes) {
    asm volatile("mbarrier.arrive.expect_tx.shared.b64 _, [%0], %1;"
                 :: "r"(mbar), "r"(bytes) : "memory");
}

__device__ __forceinline__ void bulk_load(uint32_t dst_smem, const void* src_gmem,
                                          uint32_t bytes, uint32_t mbar) {
    asm volatile(
        "cp.async.bulk.shared::cta.global.mbarrier::complete_tx::bytes [%0], [%1], %2, [%3];"
        :: "r"(dst_smem), "l"(src_gmem), "r"(bytes), "r"(mbar) : "memory");
}

__device__ __forceinline__ void bulk_store(void* dst_gmem, uint32_t src_smem,
                                           uint32_t bytes) {
    asm volatile(
        "cp.async.bulk.global.shared::cta.bulk_group [%0], [%1], %2;"
        :: "l"(dst_gmem), "r"(src_smem), "r"(bytes) : "memory");
}

__device__ __forceinline__ void bulk_commit() {
    asm volatile("cp.async.bulk.commit_group;" ::: "memory");
}

__device__ __forceinline__ void bulk_wait_all() {
    asm volatile("cp.async.bulk.wait_group 0;" ::: "memory");
}

// mbarrier wait with HW-suspend hint
__device__ __forceinline__ void mbar_wait(uint32_t mbar, uint32_t phase) {
    uint32_t done;
    asm volatile(
        "{\n\t"
        ".reg .pred p;\n\t"
        "mbarrier.try_wait.parity.acquire.cta.shared::cta.b64 p, [%1], %2, 0x989680;\n\t"
        "selp.b32 %0, 1, 0, p;\n\t"
        "}"
        : "=r"(done) : "r"(mbar), "r"(phase) : "memory");
    if (!done) {
        asm volatile(
            "{\n\t"
            ".reg .pred P1;\n\t"
            "WAIT_LOOP_%=:\n\t"
            "mbarrier.try_wait.parity.acquire.cta.shared::cta.b64 P1, [%0], %1, 0x989680;\n\t"
            "@P1 bra.uni WAIT_DONE_%=;\n\t"
            "bra.uni WAIT_LOOP_%=;\n\t"
            "WAIT_DONE_%=:\n\t"
            "}"
            :: "r"(mbar), "r"(phase) : "memory");
    }
}

__device__ __forceinline__ void fence_async_shared() {
    asm volatile("fence.proxy.async.shared::cta;" ::: "memory");
}

__device__ __forceinline__ float sgnf(float x) {
    return (float)((x > 0.0f) - (x < 0.0f));
}

// Core physics: inputs theta,vx,vy,w; outputs o[6] = {vx,vy,w,aax,aay,laz}.
__device__ __forceinline__ void process_core(float theta, float vx, float vy, float w,
                                             float md0, float md1, float md2, float md3,
                                             float o[6]) {
    // MUFU hardware sin/cos: |theta| ~ N(0,1), abs err ~1e-6 << 1e-3 gate
    float s, c;
    __sincosf(theta, &s, &c);

    const float lvx = fmaf(c, vx,  s * vy);
    const float lvy = fmaf(c, vy, -s * vx);

    const float wA = w * A_CONST;
    const float wv0 = (lvx - lvy - wA) * INV_R;
    const float wv1 = (lvx + lvy + wA) * INV_R;
    const float wv2 = (lvx + lvy - wA) * INV_R;
    const float wv3 = (lvx - lvy + wA) * INV_R;

    const float isd0 = (sgnf(md0 * wv0) + 1.0f) * 0.5f;
    const float isd1 = (sgnf(md1 * wv1) + 1.0f) * 0.5f;
    const float isd2 = (sgnf(md2 * wv2) + 1.0f) * 0.5f;
    const float isd3 = (sgnf(md3 * wv3) + 1.0f) * 0.5f;

    const float invWF = 1.0f / W_FREE_F;
    const float wt0 = T_STALL_F * (1.0f - fabsf(wv0) * isd0 * invWF) * md0;
    const float wt1 = T_STALL_F * (1.0f - fabsf(wv1) * isd1 * invWF) * md1;
    const float wt2 = T_STALL_F * (1.0f - fabsf(wv2) * isd2 * invWF) * md2;
    const float wt3 = T_STALL_F * (1.0f - fabsf(wv3) * isd3 * invWF) * md3;

    const float lax = (wt0 + wt1 + wt2 + wt3) * C_XY;
    const float lay = (-wt0 + wt1 + wt2 - wt3) * C_XY;
    const float laz = (-wt0 + wt1 - wt2 + wt3) * C_W;

    const float aax = fmaf(c, lax, -s * lay);
    const float aay = fmaf(s, lax,  c * lay);

    o[0] = vx; o[1] = vy; o[2] = w;
    o[3] = aax; o[4] = aay; o[5] = laz;
}

// Process one subtile resident in smem: thread t owns row t (6 floats at word 6t).
// Reads only the 4 live floats (theta,vx,vy,w) as 2x LDS.64; writes all 6 as 3x STS.64.
// 64-bit smem ops are half-warp phased -> lanes t and t+16 never collide on banks.
__device__ __forceinline__ void process_subtile(float* sf, int t,
                                                float md0, float md1, float md2, float md3) {
    float2* sp = (float2*)(sf + 6 * t);   // 8-byte aligned (24t % 8 == 0)
    const float2 p1 = sp[1];              // theta, vx
    const float2 p2 = sp[2];              // vy, w

    float o[6];
    process_core(p1.x, p1.y, p2.x, p2.y, md0, md1, md2, md3, o);

    sp[0] = make_float2(o[0], o[1]);
    sp[1] = make_float2(o[2], o[3]);
    sp[2] = make_float2(o[4], o[5]);
}

__global__ void __launch_bounds__(BLOCK)
mecanum_kernel(const float4* __restrict__ in4,
               const float*  __restrict__ cd,
               float4* __restrict__ out4,
               int nfull, int batch) {
    __shared__ __align__(128) float4 sbuf[2][SUB_F4];          // 2 x 6 KB
    __shared__ __align__(8)  unsigned long long mbar_storage[2];

    const int bid = blockIdx.x;
    const int t = threadIdx.x;

    // motor_duty = CD2MD @ control_duty  (uniform; L2-broadcast loads)
    const float c0 = __ldg(cd + 0), c1 = __ldg(cd + 1), c2 = __ldg(cd + 2);
    const float md0 = c0 - c1 - c2;
    const float md1 = c0 + c1 + c2;
    const float md2 = c0 + c1 - c2;
    const float md3 = c0 - c1 + c2;

    if (bid < nfull) {
        const size_t f4base = (size_t)F4_PER_BLOCK * bid;
        const uint32_t mb0 = smem_u32(&mbar_storage[0]);
        const uint32_t mb1 = smem_u32(&mbar_storage[1]);

        // issue BOTH subtile loads up front: 12 KB in flight per block
        if (t == 0) {
            mbar_init(mb0, 1);
            mbar_init(mb1, 1);
            fence_async_shared();
            mbar_expect_tx(mb0, SUB_BYTES);
            bulk_load(smem_u32(&sbuf[0][0]), (const void*)(in4 + f4base),
                      SUB_BYTES, mb0);
            mbar_expect_tx(mb1, SUB_BYTES);
            bulk_load(smem_u32(&sbuf[1][0]), (const void*)(in4 + f4base + SUB_F4),
                      SUB_BYTES, mb1);
        }
        __syncthreads();

        // ---- subtile 0 ----
        mbar_wait(mb0, 0);
        process_subtile((float*)&sbuf[0][0], t, md0, md1, md2, md3);
        __syncthreads();
        if (t == 0) {
            fence_async_shared();
            bulk_store((void*)(out4 + f4base), smem_u32(&sbuf[0][0]), SUB_BYTES);
            bulk_commit();
        }

        // ---- subtile 1 (load overlapped subtile 0's compute + store) ----
        mbar_wait(mb1, 0);
        process_subtile((float*)&sbuf[1][0], t, md0, md1, md2, md3);
        __syncthreads();
        if (t == 0) {
            fence_async_shared();
            bulk_store((void*)(out4 + f4base + SUB_F4), smem_u32(&sbuf[1][0]), SUB_BYTES);
            bulk_commit();
            bulk_wait_all();        // stores must complete before block retires
        }
    } else {
        // tail block: scalar per-row path for rows [nfull*512, batch)
        const float* inf = (const float*)in4;
        float* outf = (float*)out4;
        for (long long row = (long long)nfull * ROWS_PER_BLOCK + t;
             row < batch; row += BLOCK) {
            const long long base = row * 6;
            float o[6];
            process_core(inf[base + 2], inf[base + 3], inf[base + 4], inf[base + 5],
                         md0, md1, md2, md3, o);
            #pragma unroll
            for (int k = 0; k < 6; ++k) outf[base + k] = o[k];
        }
    }
}

extern "C" void kernel_launch(void* const* d_in, const int* in_sizes, int n_in,
                              void* d_out, int out_size) {
    // inputs: [0] t (1), [1] state (B*6), [2] control_duty (3)
    const float* state = (const float*)d_in[1];
    const float* cd    = (const float*)d_in[2];
    float* out = (float*)d_out;

    const int batch = in_sizes[1] / 6;
    const int nfull = batch / ROWS_PER_BLOCK;                 // full 512-row blocks
    const int tail  = batch - nfull * ROWS_PER_BLOCK;
    const int grid  = nfull + (tail ? 1 : 0);

    mecanum_kernel<<<grid, BLOCK>>>((const float4*)state, cd, (float4*)out,
                                    nfull, batch);
}

// round 16
// speedup vs baseline: 1.0626x; 1.0279x over previous
#include <cuda_runtime.h>
#include <cstdint>

// ---- compile-time physical constants (match reference float32 pipeline) ----
#define T_STALL_F   (5.4f * (1.0f/100.0f))                 // 0.054
#define W_FREE_F    (1620.0f * (1.0f/60.0f) * 2.0f * 3.14159265358979323846f)
#define A_CONST     (0.129907f + 0.095724f)                // L_X + L_Y
#define R_CONST     (4.0f * 0.0254f)                       // 0.1016
#define INV_R       (1.0f / R_CONST)
#define MOI_CONST   (6.0f * (12.0f*0.0254f)*(12.0f*0.0254f) / 6.0f)  // 0.09290304
#define C_XY        (INV_R / 6.0f)                         // wheel torque -> linear accel
#define C_W         ((A_CONST * INV_R) / MOI_CONST)        // wheel torque -> angular accel

#define BLOCK 256
#define ROWS_PER_TILE (2 * BLOCK)                 // 512 rows
#define F4_PER_TILE   (ROWS_PER_TILE * 6 / 4)     // 768 float4
#define TILE_BYTES    (F4_PER_TILE * 16)          // 12288 bytes

__device__ __forceinline__ uint32_t smem_u32(const void* p) {
    return (uint32_t)__cvta_generic_to_shared(p);
}

__device__ __forceinline__ void mbar_init(uint32_t mbar, uint32_t count) {
    asm volatile("mbarrier.init.shared.b64 [%0], %1;" :: "r"(mbar), "r"(count) : "memory");
}

__device__ __forceinline__ void mbar_expect_tx(uint32_t mbar, uint32_t bytes) {
    asm volatile("mbarrier.arrive.expect_tx.shared.b64 _, [%0], %1;"
                 :: "r"(mbar), "r"(bytes) : "memory");
}

// Bulk load with L2::evict_last cache hint.
__device__ __forceinline__ void bulk_load_keep(uint32_t dst_smem, const void* src_gmem,
                                               uint32_t bytes, uint32_t mbar) {
    asm volatile(
        "{\n\t"
        ".reg .b64 pol;\n\t"
        "createpolicy.fractional.L2::evict_last.b64 pol, 1.0;\n\t"
        "cp.async.bulk.shared::cta.global.mbarrier::complete_tx::bytes.L2::cache_hint "
        "[%0], [%1], %2, [%3], pol;\n\t"
        "}"
        :: "r"(dst_smem), "l"(src_gmem), "r"(bytes), "r"(mbar) : "memory");
}

// Bulk store with L2::evict_first cache hint.
__device__ __forceinline__ void bulk_store_stream(void* dst_gmem, uint32_t src_smem,
                                                  uint32_t bytes) {
    asm volatile(
        "{\n\t"
        ".reg .b64 pol;\n\t"
        "createpolicy.fractional.L2::evict_first.b64 pol, 1.0;\n\t"
        "cp.async.bulk.global.shared::cta.bulk_group.L2::cache_hint "
        "[%0], [%1], %2, pol;\n\t"
        "}"
        :: "l"(dst_gmem), "r"(src_smem), "r"(bytes) : "memory");
}

__device__ __forceinline__ void bulk_commit() {
    asm volatile("cp.async.bulk.commit_group;" ::: "memory");
}

__device__ __forceinline__ void bulk_wait_all() {
    asm volatile("cp.async.bulk.wait_group 0;" ::: "memory");
}

// mbarrier wait with HW-suspend hint
__device__ __forceinline__ void mbar_wait(uint32_t mbar, uint32_t phase) {
    uint32_t done;
    asm volatile(
        "{\n\t"
        ".reg .pred p;\n\t"
        "mbarrier.try_wait.parity.acquire.cta.shared::cta.b64 p, [%1], %2, 0x989680;\n\t"
        "selp.b32 %0, 1, 0, p;\n\t"
        "}"
        : "=r"(done) : "r"(mbar), "r"(phase) : "memory");
    if (!done) {
        asm volatile(
            "{\n\t"
            ".reg .pred P1;\n\t"
            "WAIT_LOOP_%=:\n\t"
            "mbarrier.try_wait.parity.acquire.cta.shared::cta.b64 P1, [%0], %1, 0x989680;\n\t"
            "@P1 bra.uni WAIT_DONE_%=;\n\t"
            "bra.uni WAIT_LOOP_%=;\n\t"
            "WAIT_DONE_%=:\n\t"
            "}"
            :: "r"(mbar), "r"(phase) : "memory");
    }
}

__device__ __forceinline__ void fence_async_shared() {
    asm volatile("fence.proxy.async.shared::cta;" ::: "memory");
}

__device__ __forceinline__ float sgnf(float x) {
    return (float)((x > 0.0f) - (x < 0.0f));
}

// Process one row: in r[6] = {x, y, theta, vx, vy, w}; out o[6].
__device__ __forceinline__ void process_row(const float r[6],
                                            float md0, float md1, float md2, float md3,
                                            float o[6]) {
    const float theta = r[2];
    const float vx = r[3], vy = r[4], w = r[5];

    // MUFU hardware sin/cos: |theta| ~ N(0,1), abs err ~1e-6 << 1e-3 gate
    float s, c;
    __sincosf(theta, &s, &c);

    const float lvx = fmaf(c, vx,  s * vy);
    const float lvy = fmaf(c, vy, -s * vx);

    const float wA = w * A_CONST;
    const float wv0 = (lvx - lvy - wA) * INV_R;
    const float wv1 = (lvx + lvy + wA) * INV_R;
    const float wv2 = (lvx + lvy - wA) * INV_R;
    const float wv3 = (lvx - lvy + wA) * INV_R;

    const float isd0 = (sgnf(md0 * wv0) + 1.0f) * 0.5f;
    const float isd1 = (sgnf(md1 * wv1) + 1.0f) * 0.5f;
    const float isd2 = (sgnf(md2 * wv2) + 1.0f) * 0.5f;
    const float isd3 = (sgnf(md3 * wv3) + 1.0f) * 0.5f;

    const float invWF = 1.0f / W_FREE_F;
    const float wt0 = T_STALL_F * (1.0f - fabsf(wv0) * isd0 * invWF) * md0;
    const float wt1 = T_STALL_F * (1.0f - fabsf(wv1) * isd1 * invWF) * md1;
    const float wt2 = T_STALL_F * (1.0f - fabsf(wv2) * isd2 * invWF) * md2;
    const float wt3 = T_STALL_F * (1.0f - fabsf(wv3) * isd3 * invWF) * md3;

    const float lax = (wt0 + wt1 + wt2 + wt3) * C_XY;
    const float lay = (-wt0 + wt1 + wt2 - wt3) * C_XY;
    const float laz = (-wt0 + wt1 - wt2 + wt3) * C_W;

    const float aax = fmaf(c, lax, -s * lay);
    const float aay = fmaf(s, lax,  c * lay);

    o[0] = vx; o[1] = vy; o[2] = w;
    o[3] = aax; o[4] = aay; o[5] = laz;
}

__global__ void __launch_bounds__(BLOCK)
mecanum_kernel(const float4* __restrict__ in4,
               const float*  __restrict__ cd,
               float4* __restrict__ out4,
               int nfull, int batch) {
    __shared__ __align__(128) float4 s4[F4_PER_TILE];         // 12 KB
    __shared__ __align__(8)  unsigned long long mbar_storage;

    const int bid = blockIdx.x;
    const int t = threadIdx.x;

    // motor_duty = CD2MD @ control_duty  (uniform; L2-broadcast loads)
    const float c0 = __ldg(cd + 0), c1 = __ldg(cd + 1), c2 = __ldg(cd + 2);
    const float md0 = c0 - c1 - c2;
    const float md1 = c0 + c1 + c2;
    const float md2 = c0 + c1 - c2;
    const float md3 = c0 - c1 + c2;

    if (bid < nfull) {
        const size_t f4base = (size_t)F4_PER_TILE * bid;
        const uint32_t mb = smem_u32(&mbar_storage);

        // one bulk async copy fetches the whole 12 KB tile
        if (t == 0) {
            mbar_init(mb, 1);
            fence_async_shared();
            mbar_expect_tx(mb, TILE_BYTES);
            bulk_load_keep(smem_u32(&s4[0]), (const void*)(in4 + f4base), TILE_BYTES, mb);
        }
        __syncthreads();            // mbar init visible to all threads
        mbar_wait(mb, 0);           // async->generic ordering via acquire

        // each thread: 2 rows = 3 LDS.128 at word offset 12t (conflict-free)
        float4 a = s4[3 * t + 0];
        float4 b = s4[3 * t + 1];
        float4 d = s4[3 * t + 2];

        const float r0[6] = {a.x, a.y, a.z, a.w, b.x, b.y};
        const float r1[6] = {b.z, b.w, d.x, d.y, d.z, d.w};

        float o0[6], o1[6];
        process_row(r0, md0, md1, md2, md3, o0);
        process_row(r1, md0, md1, md2, md3, o1);

        // write results back to the SAME smem words (no cross-thread hazard)
        s4[3 * t + 0] = make_float4(o0[0], o0[1], o0[2], o0[3]);
        s4[3 * t + 1] = make_float4(o0[4], o0[5], o1[0], o1[1]);
        s4[3 * t + 2] = make_float4(o1[2], o1[3], o1[4], o1[5]);
        __syncthreads();

        // one bulk async copy streams the tile back out
        if (t == 0) {
            fence_async_shared();   // generic smem writes -> async proxy
            bulk_store_stream((void*)(out4 + f4base), smem_u32(&s4[0]), TILE_BYTES);
            bulk_commit();
            bulk_wait_all();        // must complete before block retires
        }
    } else {
        // tail block: scalar per-row path for rows [nfull*512, batch)
        const float* inf = (const float*)in4;
        float* outf = (float*)out4;
        for (long long row = (long long)nfull * ROWS_PER_TILE + t;
             row < batch; row += BLOCK) {
            const long long base = row * 6;
            float r[6], o[6];
            #pragma unroll
            for (int k = 0; k < 6; ++k) r[k] = inf[base + k];
            process_row(r, md0, md1, md2, md3, o);
            #pragma unroll
            for (int k = 0; k < 6; ++k) outf[base + k] = o[k];
        }
    }
}

extern "C" void kernel_launch(void* const* d_in, const int* in_sizes, int n_in,
                              void* d_out, int out_size) {
    // inputs: [0] t (1), [1] state (B*6), [2] control_duty (3)
    const float* state = (const float*)d_in[1];
    const float* cd    = (const float*)d_in[2];
    float* out = (float*)d_out;

    const int batch = in_sizes[1] / 6;
    const int nfull = batch / ROWS_PER_TILE;                  // full tiles
    const int tail  = batch - nfull * ROWS_PER_TILE;
    const int grid  = nfull + (tail ? 1 : 0);

    mecanum_kernel<<<grid, BLOCK>>>((const float4*)state, cd, (float4*)out,
                                    nfull, batch);
}